// round 14
// baseline (speedup 1.0000x reference)
#include <cuda_runtime.h>
#include <cuda_bf16.h>
#include <math.h>
#include <float.h>
#include <stdint.h>

#define N_ROWS 100000
#define DDIM 1024
#define ADIM 128
#define HDIM 256
#define KSEL 16
#define MAXC 4096
#define NHIST 8192
#define HSHIFT 19
#define CUSH 64u
#define GEMM_BLKS 782       // ceil(100000/128)

// ================= scratch (device globals; no allocation) =================
__device__ float g_scores[N_ROWS];
__device__ __align__(16) __nv_bfloat16 g_Bbf[ADIM * DDIM];   // Wa1^T, bf16, [n][k]
__device__ __align__(16) unsigned g_hist[NHIST];
__device__ int      g_ncand;
__device__ unsigned g_thresh;
__device__ int      g_cand_i[MAXC];
__device__ float    g_cand_v[MAXC];
__device__ __align__(16) float g_cand_part[(size_t)MAXC * 8 * ADIM]; // [c][slice][n]
__device__ int      g_topidx[KSEL];
__device__ float    g_attnw[KSEL];
__device__ float    g_emb[DDIM];

__device__ __forceinline__ uint32_t smem_u32(const void* p) {
    uint32_t a;
    asm("{ .reg .u64 tmp; cvta.to.shared.u64 tmp, %1; cvt.u32.u64 %0, tmp; }"
        : "=r"(a) : "l"(p));
    return a;
}

__device__ __forceinline__ unsigned fliporder(float f) {
    unsigned u = __float_as_uint(f);
    return (u & 0x80000000u) ? ~u : (u | 0x80000000u);
}

// ================= prep: zeroing (all blocks) + Wa1 transpose (blocks 0-31) =================
__global__ void __launch_bounds__(256) prep_k(const float* __restrict__ Wa1,
                                              float* __restrict__ out,
                                              const float* __restrict__ bc2) {
    __shared__ float s[64][65];
    const int t = threadIdx.x;
    int i = blockIdx.x * 256 + t;
    if (i < N_ROWS) out[1 + DDIM + i] = 0.f;
    if (i < NHIST)  g_hist[i] = 0u;
    if (i == 0)   { g_ncand = 0; }

    if (blockIdx.x < 32) {
        const int k0 = (blockIdx.x >> 1) * 64;
        const int n0 = (blockIdx.x & 1) * 64;
#pragma unroll
        for (int e = 0; e < 16; e++) {
            int idx = e * 256 + t;
            int kk = idx >> 6, nn = idx & 63;
            s[kk][nn] = Wa1[(size_t)(k0 + kk) * ADIM + n0 + nn];
        }
        __syncthreads();
#pragma unroll
        for (int e = 0; e < 16; e++) {
            int idx = e * 256 + t;
            int nn = idx >> 6, kk = idx & 63;
            g_Bbf[(size_t)(n0 + nn) * DDIM + k0 + kk] = __float2bfloat16(s[kk][nn]);
        }
    }
}

// ================= main GEMM: approx scores via mma.sync bf16 (round-11 proven) =================
#define SROW 40   // padded row stride (bf16); 80B rows, 16B-aligned offsets

__global__ void __launch_bounds__(256, 2) gemm_scores(
    const float* __restrict__ x, const float* __restrict__ ba1,
    const float* __restrict__ Wa2, const float* __restrict__ ba2)
{
    __shared__ __align__(16) __nv_bfloat16 sA[2][128][SROW];
    __shared__ __align__(16) __nv_bfloat16 sB[2][128][SROW];
    __shared__ float s_part[4][128];
    __shared__ float s_b1[ADIM], s_w2[ADIM];

    const int t = threadIdx.x;
    const int w = t >> 5, lane = t & 31;
    const int wm = w & 1, wn = w >> 1;
    const size_t block_m = (size_t)blockIdx.x * 128;

    if (t < ADIM) { s_b1[t] = ba1[t]; s_w2[t] = Wa2[t]; }

    const int arow = t >> 3;
    const int acol = (t & 7) * 4;
    const float* xptr = x + (block_m + (size_t)arow) * DDIM + acol;
    bool aok[4];
#pragma unroll
    for (int i = 0; i < 4; i++) aok[i] = (block_m + arow + 32 * i) < N_ROWS;

    const int brow = t >> 2;
    const int bcol8 = (t & 3) * 8;
    const __nv_bfloat16* gB = g_Bbf + (size_t)brow * DDIM + bcol8;

    const int arow_l = ((lane >> 3) & 1) * 8 + (lane & 7);
    const int acol_l = (lane >> 4) * 8;
    const int brow_l = ((lane >> 4) & 1) * 8 + (lane & 7);
    const int bcol_l = ((lane >> 3) & 1) * 8;

    const uint32_t sa_base = smem_u32(&sA[0][0][0]);
    const uint32_t sb_base = smem_u32(&sB[0][0][0]);
    const uint32_t bufstride = 128 * SROW * 2;

    float acc[4][4][4];
#pragma unroll
    for (int i = 0; i < 4; i++)
#pragma unroll
        for (int j = 0; j < 4; j++)
#pragma unroll
            for (int q = 0; q < 4; q++) acc[i][j][q] = 0.f;

    float4 pa0, pa1, pa2, pa3;
    pa0 = aok[0] ? *(const float4*)(xptr)             : make_float4(0,0,0,0);
    pa1 = aok[1] ? *(const float4*)(xptr + 32 * DDIM) : make_float4(0,0,0,0);
    pa2 = aok[2] ? *(const float4*)(xptr + 64 * DDIM) : make_float4(0,0,0,0);
    pa3 = aok[3] ? *(const float4*)(xptr + 96 * DDIM) : make_float4(0,0,0,0);
    {
        uint32_t d0 = sb_base + (uint32_t)((brow * SROW + bcol8) * 2);
        uint32_t d1 = sb_base + (uint32_t)(((brow + 64) * SROW + bcol8) * 2);
        asm volatile("cp.async.cg.shared.global [%0], [%1], 16;" :: "r"(d0), "l"(gB) : "memory");
        asm volatile("cp.async.cg.shared.global [%0], [%1], 16;" :: "r"(d1), "l"(gB + 64 * DDIM) : "memory");
        asm volatile("cp.async.commit_group;" ::: "memory");
    }

#pragma unroll 1
    for (int c = 0; c < 32; c++) {
        const int buf = c & 1;
        {
            __nv_bfloat16* base = &sA[buf][0][0];
            __nv_bfloat162 q0 = __floats2bfloat162_rn(pa0.x, pa0.y);
            __nv_bfloat162 q1 = __floats2bfloat162_rn(pa0.z, pa0.w);
            *(uint2*)(base + arow * SROW + acol) = make_uint2(*(uint32_t*)&q0, *(uint32_t*)&q1);
            q0 = __floats2bfloat162_rn(pa1.x, pa1.y); q1 = __floats2bfloat162_rn(pa1.z, pa1.w);
            *(uint2*)(base + (arow + 32) * SROW + acol) = make_uint2(*(uint32_t*)&q0, *(uint32_t*)&q1);
            q0 = __floats2bfloat162_rn(pa2.x, pa2.y); q1 = __floats2bfloat162_rn(pa2.z, pa2.w);
            *(uint2*)(base + (arow + 64) * SROW + acol) = make_uint2(*(uint32_t*)&q0, *(uint32_t*)&q1);
            q0 = __floats2bfloat162_rn(pa3.x, pa3.y); q1 = __floats2bfloat162_rn(pa3.z, pa3.w);
            *(uint2*)(base + (arow + 96) * SROW + acol) = make_uint2(*(uint32_t*)&q0, *(uint32_t*)&q1);
        }
        if (c < 31) {
            const int k0 = (c + 1) * 32;
            pa0 = aok[0] ? *(const float4*)(xptr + k0)             : make_float4(0,0,0,0);
            pa1 = aok[1] ? *(const float4*)(xptr + 32 * DDIM + k0) : make_float4(0,0,0,0);
            pa2 = aok[2] ? *(const float4*)(xptr + 64 * DDIM + k0) : make_float4(0,0,0,0);
            pa3 = aok[3] ? *(const float4*)(xptr + 96 * DDIM + k0) : make_float4(0,0,0,0);
        }
        asm volatile("cp.async.wait_group 0;" ::: "memory");
        __syncthreads();
        if (c < 31) {
            const int k0 = (c + 1) * 32;
            uint32_t nb = sb_base + (uint32_t)(buf ^ 1) * bufstride;
            uint32_t d0 = nb + (uint32_t)((brow * SROW + bcol8) * 2);
            uint32_t d1 = nb + (uint32_t)(((brow + 64) * SROW + bcol8) * 2);
            asm volatile("cp.async.cg.shared.global [%0], [%1], 16;" :: "r"(d0), "l"(gB + k0) : "memory");
            asm volatile("cp.async.cg.shared.global [%0], [%1], 16;" :: "r"(d1), "l"(gB + 64 * DDIM + k0) : "memory");
            asm volatile("cp.async.commit_group;" ::: "memory");
        }
        const uint32_t sa = sa_base + buf * bufstride;
        const uint32_t sb = sb_base + buf * bufstride;
#pragma unroll
        for (int ks = 0; ks < 2; ks++) {
            uint32_t a[4][4];
#pragma unroll
            for (int mi = 0; mi < 4; mi++) {
                uint32_t addr = sa + (((wm * 64 + mi * 16 + arow_l) * SROW) + ks * 16 + acol_l) * 2;
                asm volatile("ldmatrix.sync.aligned.m8n8.x4.shared.b16 {%0,%1,%2,%3}, [%4];"
                    : "=r"(a[mi][0]), "=r"(a[mi][1]), "=r"(a[mi][2]), "=r"(a[mi][3]) : "r"(addr));
            }
            uint32_t b[4][2];
#pragma unroll
            for (int njp = 0; njp < 2; njp++) {
                uint32_t addr = sb + (((wn * 32 + njp * 16 + brow_l) * SROW) + ks * 16 + bcol_l) * 2;
                uint32_t r0, r1, r2, r3;
                asm volatile("ldmatrix.sync.aligned.m8n8.x4.shared.b16 {%0,%1,%2,%3}, [%4];"
                    : "=r"(r0), "=r"(r1), "=r"(r2), "=r"(r3) : "r"(addr));
                b[njp * 2 + 0][0] = r0; b[njp * 2 + 0][1] = r1;
                b[njp * 2 + 1][0] = r2; b[njp * 2 + 1][1] = r3;
            }
#pragma unroll
            for (int mi = 0; mi < 4; mi++)
#pragma unroll
                for (int nj = 0; nj < 4; nj++) {
                    asm volatile(
                        "mma.sync.aligned.m16n8k16.row.col.f32.bf16.bf16.f32 "
                        "{%0,%1,%2,%3}, {%4,%5,%6,%7}, {%8,%9}, {%0,%1,%2,%3};"
                        : "+f"(acc[mi][nj][0]), "+f"(acc[mi][nj][1]),
                          "+f"(acc[mi][nj][2]), "+f"(acc[mi][nj][3])
                        : "r"(a[mi][0]), "r"(a[mi][1]), "r"(a[mi][2]), "r"(a[mi][3]),
                          "r"(b[nj][0]), "r"(b[nj][1]));
                }
        }
    }

    __syncthreads();
#pragma unroll
    for (int mi = 0; mi < 4; mi++) {
        float p0 = 0.f, p1 = 0.f;
#pragma unroll
        for (int nj = 0; nj < 4; nj++) {
            int col = wn * 32 + nj * 8 + (lane & 3) * 2;
            float th;
            float v0 = acc[mi][nj][0] + s_b1[col];
            asm("tanh.approx.f32 %0, %1;" : "=f"(th) : "f"(v0));
            p0 = fmaf(th, s_w2[col], p0);
            float v1 = acc[mi][nj][1] + s_b1[col + 1];
            asm("tanh.approx.f32 %0, %1;" : "=f"(th) : "f"(v1));
            p0 = fmaf(th, s_w2[col + 1], p0);
            float v2 = acc[mi][nj][2] + s_b1[col];
            asm("tanh.approx.f32 %0, %1;" : "=f"(th) : "f"(v2));
            p1 = fmaf(th, s_w2[col], p1);
            float v3 = acc[mi][nj][3] + s_b1[col + 1];
            asm("tanh.approx.f32 %0, %1;" : "=f"(th) : "f"(v3));
            p1 = fmaf(th, s_w2[col + 1], p1);
        }
        p0 += __shfl_xor_sync(0xffffffffu, p0, 1);
        p0 += __shfl_xor_sync(0xffffffffu, p0, 2);
        p1 += __shfl_xor_sync(0xffffffffu, p1, 1);
        p1 += __shfl_xor_sync(0xffffffffu, p1, 2);
        if ((lane & 3) == 0) {
            int r = wm * 64 + mi * 16 + (lane >> 2);
            s_part[wn][r]     = p0;
            s_part[wn][r + 8] = p1;
        }
    }
    __syncthreads();
    if (t < 128) {
        size_t m = block_m + (size_t)t;
        if (m < N_ROWS) {
            float sc = s_part[0][t] + s_part[1][t] + s_part[2][t] + s_part[3][t] + ba2[0];
            g_scores[m] = sc;
            atomicAdd(&g_hist[fliporder(sc) >> HSHIFT], 1u);
        }
    }
}

// ================= scan: 1024 threads, 8 bins/thread, parallel suffix-scan =================
__global__ void __launch_bounds__(1024) scan_k() {
    __shared__ unsigned s_wsum[32];
    __shared__ int s_seg;
    __shared__ unsigned s_cum;
    const int t = threadIdx.x;
    const int lane = t & 31, wid = t >> 5;

    // 8 bins per thread via two uint4 loads (coalesced-ish, high MLP)
    uint4 h0 = *(const uint4*)&g_hist[t * 8];
    uint4 h1 = *(const uint4*)&g_hist[t * 8 + 4];
    unsigned part = h0.x + h0.y + h0.z + h0.w + h1.x + h1.y + h1.z + h1.w;

    unsigned sfx = part;
#pragma unroll
    for (int off = 1; off < 32; off <<= 1) {
        unsigned v = __shfl_down_sync(0xffffffffu, sfx, off);
        if (lane + off < 32) sfx += v;
    }
    if (lane == 0) s_wsum[wid] = sfx;
    __syncthreads();
    unsigned above = 0;
    for (int ww = wid + 1; ww < 32; ww++) above += s_wsum[ww];
    unsigned ssum = sfx + above;
    if (ssum >= CUSH && (ssum - part) < CUSH) { s_seg = t; s_cum = ssum - part; }
    __syncthreads();
    if (t < 8) {
        // thread t owns bin s_seg*8 + t; serial-in-warp suffix over 8 bins
        unsigned bins[8];
#pragma unroll
        for (int j = 0; j < 8; j++) bins[j] = g_hist[s_seg * 8 + j];
        if (t == 0) {
            unsigned cum = s_cum;
            int b = 7;
            for (; b > 0; b--) { cum += bins[b]; if (cum >= CUSH) break; }
            g_thresh = ((unsigned)(s_seg * 8 + b)) << HSHIFT;
        }
    }
}

// ================= collect: stream against precomputed threshold =================
__global__ void __launch_bounds__(256) collect_k() {
    const unsigned thresh = g_thresh;
    int i = blockIdx.x * 256 + threadIdx.x;
    if (i < N_ROWS && fliporder(g_scores[i]) >= thresh) {
        int p = atomicAdd(&g_ncand, 1);
        if (p < MAXC) g_cand_i[p] = i;
    }
}

// ================= rescore phase 1: split-K (8 slices of 128) =================
__global__ void __launch_bounds__(128) rescore_part(
    const float* __restrict__ x, const float* __restrict__ Wa1)
{
    __shared__ float sx[128];
    int nc = g_ncand; if (nc > MAXC) nc = MAXC;
    const int nwork = nc * 8;
    const int t = threadIdx.x;
    for (int wk = blockIdx.x; wk < nwork; wk += gridDim.x) {
        const int c = wk >> 3, s = wk & 7;
        const int row = g_cand_i[c];
        sx[t] = x[(size_t)row * DDIM + s * 128 + t];
        __syncthreads();
        const float* Wp = Wa1 + (size_t)(s * 128) * ADIM + t;
        float a = 0.f;
#pragma unroll 8
        for (int k = 0; k < 128; k++)
            a = fmaf(sx[k], Wp[(size_t)k * ADIM], a);
        g_cand_part[((size_t)c * 8 + s) * ADIM + t] = a;
        __syncthreads();
    }
}

// ================= rescore phase 2: combine partials, tanh, reduce =================
__global__ void __launch_bounds__(128) rescore_fin(
    const float* __restrict__ ba1, const float* __restrict__ Wa2,
    const float* __restrict__ ba2)
{
    __shared__ float sred[4];
    int nc = g_ncand; if (nc > MAXC) nc = MAXC;
    const int t = threadIdx.x;
    const float b1 = ba1[t], w2 = Wa2[t], b2 = ba2[0];
    for (int c = blockIdx.x; c < nc; c += gridDim.x) {
        const float* p = g_cand_part + (size_t)c * 8 * ADIM;
        float a = 0.f;
#pragma unroll
        for (int j = 0; j < 8; j++) a += p[j * ADIM + t];
        float v = tanhf(a + b1) * w2;
#pragma unroll
        for (int off = 16; off >= 1; off >>= 1)
            v += __shfl_down_sync(0xffffffffu, v, off);
        if ((t & 31) == 0) sred[t >> 5] = v;
        __syncthreads();
        if (t == 0) g_cand_v[c] = sred[0] + sred[1] + sred[2] + sred[3] + b2;
        __syncthreads();
    }
}

// ================= tail: top-16 + softmax + scatter + embedding + classifier =================
__global__ void __launch_bounds__(256) tail_k(const float* __restrict__ x,
                                              const float* __restrict__ Wc1,
                                              const float* __restrict__ bc1,
                                              const float* __restrict__ Wc2,
                                              const float* __restrict__ bc2,
                                              float* __restrict__ out) {
    __shared__ float sv[MAXC];
    __shared__ int   si[MAXC];
    __shared__ float wv[8];
    __shared__ int   wi[8];
    __shared__ float topv[KSEL];
    __shared__ int   topi[KSEL];
    __shared__ float topw[KSEL];
    __shared__ float s_emb[DDIM];
    __shared__ float s_red[8];
    const int t = threadIdx.x;
    int nc = g_ncand; if (nc > MAXC) nc = MAXC;
    for (int i = t; i < nc; i += 256) { sv[i] = g_cand_v[i]; si[i] = g_cand_i[i]; }
    __syncthreads();
    for (int it = 0; it < KSEL; it++) {
        float bv = -FLT_MAX; int bi = 0x7fffffff;
        for (int i = t; i < nc; i += 256) {
            float v = sv[i]; int gi = si[i];
            if (v > bv || (v == bv && gi < bi)) { bv = v; bi = gi; }
        }
#pragma unroll
        for (int off = 16; off >= 1; off >>= 1) {
            float ov = __shfl_down_sync(0xffffffffu, bv, off);
            int   oi = __shfl_down_sync(0xffffffffu, bi, off);
            if (ov > bv || (ov == bv && oi < bi)) { bv = ov; bi = oi; }
        }
        if ((t & 31) == 0) { wv[t >> 5] = bv; wi[t >> 5] = bi; }
        __syncthreads();
        if (t == 0) {
            for (int w = 1; w < 8; w++)
                if (wv[w] > wv[0] || (wv[w] == wv[0] && wi[w] < wi[0])) { wv[0] = wv[w]; wi[0] = wi[w]; }
            topv[it] = wv[0]; topi[it] = wi[0];
        }
        __syncthreads();
        int wini = topi[it];
        for (int i = t; i < nc; i += 256)
            if (si[i] == wini) sv[i] = -FLT_MAX;
        __syncthreads();
    }
    if (t == 0) {
        float m = topv[0];
        float e[KSEL];
        float ssum = 0.f;
        for (int j = 0; j < KSEL; j++) { e[j] = expf(topv[j] - m); ssum += e[j]; }
        float inv = 1.f / ssum;
        for (int j = 0; j < KSEL; j++) {
            float wgt = e[j] * inv;
            topw[j] = wgt;
            g_attnw[j]  = wgt;
            g_topidx[j] = topi[j];
            out[1 + DDIM + N_ROWS + j] = (float)topi[j];
            out[1 + DDIM + topi[j]]    = wgt;
        }
    }
    __syncthreads();
    // embedding
    for (int d = t; d < DDIM; d += 256) {
        float s = 0.f;
#pragma unroll
        for (int j = 0; j < KSEL; j++)
            s += topw[j] * x[(size_t)topi[j] * DDIM + d];
        s_emb[d]   = s;
        out[1 + d] = s;
    }
    __syncthreads();
    // classifier: thread t owns h-column t (HDIM=256)
    {
        float acc = 0.f;
#pragma unroll 8
        for (int d = 0; d < DDIM; d++)
            acc = fmaf(s_emb[d], Wc1[(size_t)d * HDIM + t], acc);
        float h = fmaxf(acc + bc1[t], 0.f);
        float part = h * Wc2[t];
#pragma unroll
        for (int off = 16; off >= 1; off >>= 1)
            part += __shfl_down_sync(0xffffffffu, part, off);
        if ((t & 31) == 0) s_red[t >> 5] = part;
        __syncthreads();
        if (t == 0)
            out[0] = s_red[0] + s_red[1] + s_red[2] + s_red[3]
                   + s_red[4] + s_red[5] + s_red[6] + s_red[7] + bc2[0];
    }
}

// ================= launch =================
extern "C" void kernel_launch(void* const* d_in, const int* in_sizes, int n_in,
                              void* d_out, int out_size)
{
    const float* x   = (const float*)d_in[0];
    const float* Wa1 = (const float*)d_in[1];
    const float* ba1 = (const float*)d_in[2];
    const float* Wa2 = (const float*)d_in[3];
    const float* ba2 = (const float*)d_in[4];
    const float* Wc1 = (const float*)d_in[5];
    const float* bc1 = (const float*)d_in[6];
    const float* Wc2 = (const float*)d_in[7];
    const float* bc2 = (const float*)d_in[8];
    float* out = (float*)d_out;

    prep_k<<<391, 256>>>(Wa1, out, bc2);
    gemm_scores<<<GEMM_BLKS, 256>>>(x, ba1, Wa2, ba2);
    scan_k<<<1, 1024>>>();
    collect_k<<<391, 256>>>();
    rescore_part<<<1184, 128>>>(x, Wa1);
    rescore_fin<<<148, 128>>>(ba1, Wa2, ba2);
    tail_k<<<1, 256>>>(x, Wc1, bc1, Wc2, bc2, out);
}

// round 15
// speedup vs baseline: 1.3959x; 1.3959x over previous
#include <cuda_runtime.h>
#include <cuda_bf16.h>
#include <math.h>
#include <float.h>
#include <stdint.h>

#define N_ROWS 100000
#define DDIM 1024
#define ADIM 128
#define HDIM 256
#define KSEL 16
#define MAXC 4096
#define NHIST 8192
#define HSHIFT 19
#define CUSH 64u
#define GEMM_BLKS 782       // ceil(100000/128)

// ================= scratch (device globals; no allocation) =================
__device__ float g_scores[N_ROWS];
__device__ __align__(16) __nv_bfloat16 g_Bbf[ADIM * DDIM];   // Wa1^T, bf16, [n][k]
__device__ unsigned g_hist[NHIST];
__device__ int      g_ncand;
__device__ unsigned g_thresh;
__device__ int      g_cand_i[MAXC];
__device__ float    g_cand_v[MAXC];
__device__ __align__(16) float g_cand_part[(size_t)MAXC * 8 * ADIM]; // [c][slice][n]
__device__ int      g_topidx[KSEL];
__device__ float    g_attnw[KSEL];
__device__ float    g_emb[DDIM];

__device__ __forceinline__ uint32_t smem_u32(const void* p) {
    uint32_t a;
    asm("{ .reg .u64 tmp; cvta.to.shared.u64 tmp, %1; cvt.u32.u64 %0, tmp; }"
        : "=r"(a) : "l"(p));
    return a;
}

__device__ __forceinline__ unsigned fliporder(float f) {
    unsigned u = __float_as_uint(f);
    return (u & 0x80000000u) ? ~u : (u | 0x80000000u);
}

// ================= prep: zeroing (all blocks) + Wa1 transpose (blocks 0-31) =================
__global__ void __launch_bounds__(256) prep_k(const float* __restrict__ Wa1,
                                              float* __restrict__ out,
                                              const float* __restrict__ bc2) {
    __shared__ float s[64][65];
    const int t = threadIdx.x;
    int i = blockIdx.x * 256 + t;
    if (i < N_ROWS) out[1 + DDIM + i] = 0.f;
    if (i < NHIST)  g_hist[i] = 0u;
    if (i == 0)   { g_ncand = 0; out[0] = bc2[0]; }

    if (blockIdx.x < 32) {
        const int k0 = (blockIdx.x >> 1) * 64;
        const int n0 = (blockIdx.x & 1) * 64;
#pragma unroll
        for (int e = 0; e < 16; e++) {
            int idx = e * 256 + t;
            int kk = idx >> 6, nn = idx & 63;
            s[kk][nn] = Wa1[(size_t)(k0 + kk) * ADIM + n0 + nn];
        }
        __syncthreads();
#pragma unroll
        for (int e = 0; e < 16; e++) {
            int idx = e * 256 + t;
            int nn = idx >> 6, kk = idx & 63;
            g_Bbf[(size_t)(n0 + nn) * DDIM + k0 + kk] = __float2bfloat16(s[kk][nn]);
        }
    }
}

// ================= main GEMM: approx scores via mma.sync bf16 (round-11 proven) =================
#define SROW 40   // padded row stride (bf16); 80B rows, 16B-aligned offsets

__global__ void __launch_bounds__(256, 2) gemm_scores(
    const float* __restrict__ x, const float* __restrict__ ba1,
    const float* __restrict__ Wa2, const float* __restrict__ ba2)
{
    __shared__ __align__(16) __nv_bfloat16 sA[2][128][SROW];
    __shared__ __align__(16) __nv_bfloat16 sB[2][128][SROW];
    __shared__ float s_part[4][128];
    __shared__ float s_b1[ADIM], s_w2[ADIM];

    const int t = threadIdx.x;
    const int w = t >> 5, lane = t & 31;
    const int wm = w & 1, wn = w >> 1;
    const size_t block_m = (size_t)blockIdx.x * 128;

    if (t < ADIM) { s_b1[t] = ba1[t]; s_w2[t] = Wa2[t]; }

    const int arow = t >> 3;
    const int acol = (t & 7) * 4;
    const float* xptr = x + (block_m + (size_t)arow) * DDIM + acol;
    bool aok[4];
#pragma unroll
    for (int i = 0; i < 4; i++) aok[i] = (block_m + arow + 32 * i) < N_ROWS;

    const int brow = t >> 2;
    const int bcol8 = (t & 3) * 8;
    const __nv_bfloat16* gB = g_Bbf + (size_t)brow * DDIM + bcol8;

    const int arow_l = ((lane >> 3) & 1) * 8 + (lane & 7);
    const int acol_l = (lane >> 4) * 8;
    const int brow_l = ((lane >> 4) & 1) * 8 + (lane & 7);
    const int bcol_l = ((lane >> 3) & 1) * 8;

    const uint32_t sa_base = smem_u32(&sA[0][0][0]);
    const uint32_t sb_base = smem_u32(&sB[0][0][0]);
    const uint32_t bufstride = 128 * SROW * 2;

    float acc[4][4][4];
#pragma unroll
    for (int i = 0; i < 4; i++)
#pragma unroll
        for (int j = 0; j < 4; j++)
#pragma unroll
            for (int q = 0; q < 4; q++) acc[i][j][q] = 0.f;

    float4 pa0, pa1, pa2, pa3;
    pa0 = aok[0] ? *(const float4*)(xptr)             : make_float4(0,0,0,0);
    pa1 = aok[1] ? *(const float4*)(xptr + 32 * DDIM) : make_float4(0,0,0,0);
    pa2 = aok[2] ? *(const float4*)(xptr + 64 * DDIM) : make_float4(0,0,0,0);
    pa3 = aok[3] ? *(const float4*)(xptr + 96 * DDIM) : make_float4(0,0,0,0);
    {
        uint32_t d0 = sb_base + (uint32_t)((brow * SROW + bcol8) * 2);
        uint32_t d1 = sb_base + (uint32_t)(((brow + 64) * SROW + bcol8) * 2);
        asm volatile("cp.async.cg.shared.global [%0], [%1], 16;" :: "r"(d0), "l"(gB) : "memory");
        asm volatile("cp.async.cg.shared.global [%0], [%1], 16;" :: "r"(d1), "l"(gB + 64 * DDIM) : "memory");
        asm volatile("cp.async.commit_group;" ::: "memory");
    }

#pragma unroll 1
    for (int c = 0; c < 32; c++) {
        const int buf = c & 1;
        {
            __nv_bfloat16* base = &sA[buf][0][0];
            __nv_bfloat162 q0 = __floats2bfloat162_rn(pa0.x, pa0.y);
            __nv_bfloat162 q1 = __floats2bfloat162_rn(pa0.z, pa0.w);
            *(uint2*)(base + arow * SROW + acol) = make_uint2(*(uint32_t*)&q0, *(uint32_t*)&q1);
            q0 = __floats2bfloat162_rn(pa1.x, pa1.y); q1 = __floats2bfloat162_rn(pa1.z, pa1.w);
            *(uint2*)(base + (arow + 32) * SROW + acol) = make_uint2(*(uint32_t*)&q0, *(uint32_t*)&q1);
            q0 = __floats2bfloat162_rn(pa2.x, pa2.y); q1 = __floats2bfloat162_rn(pa2.z, pa2.w);
            *(uint2*)(base + (arow + 64) * SROW + acol) = make_uint2(*(uint32_t*)&q0, *(uint32_t*)&q1);
            q0 = __floats2bfloat162_rn(pa3.x, pa3.y); q1 = __floats2bfloat162_rn(pa3.z, pa3.w);
            *(uint2*)(base + (arow + 96) * SROW + acol) = make_uint2(*(uint32_t*)&q0, *(uint32_t*)&q1);
        }
        if (c < 31) {
            const int k0 = (c + 1) * 32;
            pa0 = aok[0] ? *(const float4*)(xptr + k0)             : make_float4(0,0,0,0);
            pa1 = aok[1] ? *(const float4*)(xptr + 32 * DDIM + k0) : make_float4(0,0,0,0);
            pa2 = aok[2] ? *(const float4*)(xptr + 64 * DDIM + k0) : make_float4(0,0,0,0);
            pa3 = aok[3] ? *(const float4*)(xptr + 96 * DDIM + k0) : make_float4(0,0,0,0);
        }
        asm volatile("cp.async.wait_group 0;" ::: "memory");
        __syncthreads();
        if (c < 31) {
            const int k0 = (c + 1) * 32;
            uint32_t nb = sb_base + (uint32_t)(buf ^ 1) * bufstride;
            uint32_t d0 = nb + (uint32_t)((brow * SROW + bcol8) * 2);
            uint32_t d1 = nb + (uint32_t)(((brow + 64) * SROW + bcol8) * 2);
            asm volatile("cp.async.cg.shared.global [%0], [%1], 16;" :: "r"(d0), "l"(gB + k0) : "memory");
            asm volatile("cp.async.cg.shared.global [%0], [%1], 16;" :: "r"(d1), "l"(gB + 64 * DDIM + k0) : "memory");
            asm volatile("cp.async.commit_group;" ::: "memory");
        }
        const uint32_t sa = sa_base + buf * bufstride;
        const uint32_t sb = sb_base + buf * bufstride;
#pragma unroll
        for (int ks = 0; ks < 2; ks++) {
            uint32_t a[4][4];
#pragma unroll
            for (int mi = 0; mi < 4; mi++) {
                uint32_t addr = sa + (((wm * 64 + mi * 16 + arow_l) * SROW) + ks * 16 + acol_l) * 2;
                asm volatile("ldmatrix.sync.aligned.m8n8.x4.shared.b16 {%0,%1,%2,%3}, [%4];"
                    : "=r"(a[mi][0]), "=r"(a[mi][1]), "=r"(a[mi][2]), "=r"(a[mi][3]) : "r"(addr));
            }
            uint32_t b[4][2];
#pragma unroll
            for (int njp = 0; njp < 2; njp++) {
                uint32_t addr = sb + (((wn * 32 + njp * 16 + brow_l) * SROW) + ks * 16 + bcol_l) * 2;
                uint32_t r0, r1, r2, r3;
                asm volatile("ldmatrix.sync.aligned.m8n8.x4.shared.b16 {%0,%1,%2,%3}, [%4];"
                    : "=r"(r0), "=r"(r1), "=r"(r2), "=r"(r3) : "r"(addr));
                b[njp * 2 + 0][0] = r0; b[njp * 2 + 0][1] = r1;
                b[njp * 2 + 1][0] = r2; b[njp * 2 + 1][1] = r3;
            }
#pragma unroll
            for (int mi = 0; mi < 4; mi++)
#pragma unroll
                for (int nj = 0; nj < 4; nj++) {
                    asm volatile(
                        "mma.sync.aligned.m16n8k16.row.col.f32.bf16.bf16.f32 "
                        "{%0,%1,%2,%3}, {%4,%5,%6,%7}, {%8,%9}, {%0,%1,%2,%3};"
                        : "+f"(acc[mi][nj][0]), "+f"(acc[mi][nj][1]),
                          "+f"(acc[mi][nj][2]), "+f"(acc[mi][nj][3])
                        : "r"(a[mi][0]), "r"(a[mi][1]), "r"(a[mi][2]), "r"(a[mi][3]),
                          "r"(b[nj][0]), "r"(b[nj][1]));
                }
        }
    }

    __syncthreads();
#pragma unroll
    for (int mi = 0; mi < 4; mi++) {
        float p0 = 0.f, p1 = 0.f;
#pragma unroll
        for (int nj = 0; nj < 4; nj++) {
            int col = wn * 32 + nj * 8 + (lane & 3) * 2;
            float th;
            float v0 = acc[mi][nj][0] + s_b1[col];
            asm("tanh.approx.f32 %0, %1;" : "=f"(th) : "f"(v0));
            p0 = fmaf(th, s_w2[col], p0);
            float v1 = acc[mi][nj][1] + s_b1[col + 1];
            asm("tanh.approx.f32 %0, %1;" : "=f"(th) : "f"(v1));
            p0 = fmaf(th, s_w2[col + 1], p0);
            float v2 = acc[mi][nj][2] + s_b1[col];
            asm("tanh.approx.f32 %0, %1;" : "=f"(th) : "f"(v2));
            p1 = fmaf(th, s_w2[col], p1);
            float v3 = acc[mi][nj][3] + s_b1[col + 1];
            asm("tanh.approx.f32 %0, %1;" : "=f"(th) : "f"(v3));
            p1 = fmaf(th, s_w2[col + 1], p1);
        }
        p0 += __shfl_xor_sync(0xffffffffu, p0, 1);
        p0 += __shfl_xor_sync(0xffffffffu, p0, 2);
        p1 += __shfl_xor_sync(0xffffffffu, p1, 1);
        p1 += __shfl_xor_sync(0xffffffffu, p1, 2);
        if ((lane & 3) == 0) {
            int r = wm * 64 + mi * 16 + (lane >> 2);
            s_part[wn][r]     = p0;
            s_part[wn][r + 8] = p1;
        }
    }
    __syncthreads();
    if (t < 128) {
        size_t m = block_m + (size_t)t;
        if (m < N_ROWS) {
            float sc = s_part[0][t] + s_part[1][t] + s_part[2][t] + s_part[3][t] + ba2[0];
            g_scores[m] = sc;
            atomicAdd(&g_hist[fliporder(sc) >> HSHIFT], 1u);
        }
    }
}

// ================= scan: ONE block, parallel suffix-scan -> g_thresh =================
__global__ void __launch_bounds__(256) scan_k() {
    __shared__ unsigned s_wsum[8];
    __shared__ int s_seg;
    __shared__ unsigned s_cum;
    const int t = threadIdx.x;
    const int lane = t & 31, wid = t >> 5;

    unsigned part = 0;
#pragma unroll
    for (int j = 0; j < 32; j++) part += g_hist[t * 32 + j];

    unsigned sfx = part;
#pragma unroll
    for (int off = 1; off < 32; off <<= 1) {
        unsigned v = __shfl_down_sync(0xffffffffu, sfx, off);
        if (lane + off < 32) sfx += v;
    }
    if (lane == 0) s_wsum[wid] = sfx;
    __syncthreads();
    unsigned above = 0;
    for (int ww = wid + 1; ww < 8; ww++) above += s_wsum[ww];
    unsigned ssum = sfx + above;
    if (ssum >= CUSH && (ssum - part) < CUSH) { s_seg = t; s_cum = ssum - part; }
    __syncthreads();
    if (wid == 0) {
        unsigned bin = g_hist[s_seg * 32 + lane];
        unsigned bs = bin;
#pragma unroll
        for (int off = 1; off < 32; off <<= 1) {
            unsigned v = __shfl_down_sync(0xffffffffu, bs, off);
            if (lane + off < 32) bs += v;
        }
        unsigned tot = s_cum + bs;
        unsigned totn = tot - bin;
        if (tot >= CUSH && totn < CUSH)
            g_thresh = ((unsigned)(s_seg * 32 + lane)) << HSHIFT;
    }
}

// ================= collect: stream against precomputed threshold =================
__global__ void __launch_bounds__(256) collect_k() {
    const unsigned thresh = g_thresh;
    int i = blockIdx.x * 256 + threadIdx.x;
    if (i < N_ROWS && fliporder(g_scores[i]) >= thresh) {
        int p = atomicAdd(&g_ncand, 1);
        if (p < MAXC) g_cand_i[p] = i;
    }
}

// ================= rescore phase 1: split-K (8 slices of 128) =================
__global__ void __launch_bounds__(128) rescore_part(
    const float* __restrict__ x, const float* __restrict__ Wa1)
{
    __shared__ float sx[128];
    int nc = g_ncand; if (nc > MAXC) nc = MAXC;
    const int nwork = nc * 8;
    const int t = threadIdx.x;
    for (int wk = blockIdx.x; wk < nwork; wk += gridDim.x) {
        const int c = wk >> 3, s = wk & 7;
        const int row = g_cand_i[c];
        sx[t] = x[(size_t)row * DDIM + s * 128 + t];
        __syncthreads();
        const float* Wp = Wa1 + (size_t)(s * 128) * ADIM + t;
        float a = 0.f;
#pragma unroll 8
        for (int k = 0; k < 128; k++)
            a = fmaf(sx[k], Wp[(size_t)k * ADIM], a);
        g_cand_part[((size_t)c * 8 + s) * ADIM + t] = a;
        __syncthreads();
    }
}

// ================= rescore phase 2: combine partials, tanh, reduce =================
__global__ void __launch_bounds__(128) rescore_fin(
    const float* __restrict__ ba1, const float* __restrict__ Wa2,
    const float* __restrict__ ba2)
{
    __shared__ float sred[4];
    int nc = g_ncand; if (nc > MAXC) nc = MAXC;
    const int t = threadIdx.x;
    const float b1 = ba1[t], w2 = Wa2[t], b2 = ba2[0];
    for (int c = blockIdx.x; c < nc; c += gridDim.x) {
        const float* p = g_cand_part + (size_t)c * 8 * ADIM;
        float a = 0.f;
#pragma unroll
        for (int j = 0; j < 8; j++) a += p[j * ADIM + t];
        float v = tanhf(a + b1) * w2;
#pragma unroll
        for (int off = 16; off >= 1; off >>= 1)
            v += __shfl_down_sync(0xffffffffu, v, off);
        if ((t & 31) == 0) sred[t >> 5] = v;
        __syncthreads();
        if (t == 0) g_cand_v[c] = sred[0] + sred[1] + sred[2] + sred[3] + b2;
        __syncthreads();
    }
}

// ================= tail: exact top-16 + softmax + scatter + embedding =================
__global__ void __launch_bounds__(256) tail_k(const float* __restrict__ x,
                                              float* __restrict__ out) {
    __shared__ float sv[MAXC];
    __shared__ int   si[MAXC];
    __shared__ float wv[8];
    __shared__ int   wi[8];
    __shared__ float topv[KSEL];
    __shared__ int   topi[KSEL];
    __shared__ float topw[KSEL];
    const int t = threadIdx.x;
    int nc = g_ncand; if (nc > MAXC) nc = MAXC;
    for (int i = t; i < nc; i += 256) { sv[i] = g_cand_v[i]; si[i] = g_cand_i[i]; }
    __syncthreads();
    for (int it = 0; it < KSEL; it++) {
        float bv = -FLT_MAX; int bi = 0x7fffffff;
        for (int i = t; i < nc; i += 256) {
            float v = sv[i]; int gi = si[i];
            if (v > bv || (v == bv && gi < bi)) { bv = v; bi = gi; }
        }
#pragma unroll
        for (int off = 16; off >= 1; off >>= 1) {
            float ov = __shfl_down_sync(0xffffffffu, bv, off);
            int   oi = __shfl_down_sync(0xffffffffu, bi, off);
            if (ov > bv || (ov == bv && oi < bi)) { bv = ov; bi = oi; }
        }
        if ((t & 31) == 0) { wv[t >> 5] = bv; wi[t >> 5] = bi; }
        __syncthreads();
        if (t == 0) {
            for (int w = 1; w < 8; w++)
                if (wv[w] > wv[0] || (wv[w] == wv[0] && wi[w] < wi[0])) { wv[0] = wv[w]; wi[0] = wi[w]; }
            topv[it] = wv[0]; topi[it] = wi[0];
        }
        __syncthreads();
        int wini = topi[it];
        for (int i = t; i < nc; i += 256)
            if (si[i] == wini) sv[i] = -FLT_MAX;
        __syncthreads();
    }
    if (t == 0) {
        float m = topv[0];
        float e[KSEL];
        float ssum = 0.f;
        for (int j = 0; j < KSEL; j++) { e[j] = expf(topv[j] - m); ssum += e[j]; }
        float inv = 1.f / ssum;
        for (int j = 0; j < KSEL; j++) {
            float wgt = e[j] * inv;
            topw[j] = wgt;
            g_attnw[j]  = wgt;
            g_topidx[j] = topi[j];
            out[1 + DDIM + N_ROWS + j] = (float)topi[j];
            out[1 + DDIM + topi[j]]    = wgt;
        }
    }
    __syncthreads();
    for (int d = t; d < DDIM; d += 256) {
        float s = 0.f;
#pragma unroll
        for (int j = 0; j < KSEL; j++)
            s += topw[j] * x[(size_t)topi[j] * DDIM + d];
        g_emb[d]   = s;
        out[1 + d] = s;
    }
}

// ================= classifier: 8 blocks, partial logits via atomicAdd =================
__global__ void __launch_bounds__(256) cls_kernel(
    const float* __restrict__ Wc1, const float* __restrict__ bc1,
    const float* __restrict__ Wc2, float* __restrict__ out)
{
    __shared__ float e[DDIM];
    __shared__ float sred[8][32];
    const int t = threadIdx.x;
    const int j = blockIdx.x * 32 + (t & 31);
    const int dp = (t >> 5) * 128;
    for (int d = t; d < DDIM; d += 256) e[d] = g_emb[d];
    __syncthreads();
    float acc = 0.f;
#pragma unroll 16
    for (int d = 0; d < 128; d++)
        acc = fmaf(e[dp + d], Wc1[(size_t)(dp + d) * HDIM + j], acc);
    sred[t >> 5][t & 31] = acc;
    __syncthreads();
    if (t < 32) {
        float a = sred[0][t] + sred[1][t] + sred[2][t] + sred[3][t]
                + sred[4][t] + sred[5][t] + sred[6][t] + sred[7][t];
        int jj = blockIdx.x * 32 + t;
        float h = fmaxf(a + bc1[jj], 0.f);
        float part = h * Wc2[jj];
#pragma unroll
        for (int off = 16; off >= 1; off >>= 1)
            part += __shfl_down_sync(0xffffffffu, part, off);
        if (t == 0) atomicAdd(out, part);
    }
}

// ================= launch =================
extern "C" void kernel_launch(void* const* d_in, const int* in_sizes, int n_in,
                              void* d_out, int out_size)
{
    const float* x   = (const float*)d_in[0];
    const float* Wa1 = (const float*)d_in[1];
    const float* ba1 = (const float*)d_in[2];
    const float* Wa2 = (const float*)d_in[3];
    const float* ba2 = (const float*)d_in[4];
    const float* Wc1 = (const float*)d_in[5];
    const float* bc1 = (const float*)d_in[6];
    const float* Wc2 = (const float*)d_in[7];
    const float* bc2 = (const float*)d_in[8];
    float* out = (float*)d_out;

    prep_k<<<391, 256>>>(Wa1, out, bc2);
    gemm_scores<<<GEMM_BLKS, 256>>>(x, ba1, Wa2, ba2);
    scan_k<<<1, 256>>>();
    collect_k<<<391, 256>>>();
    rescore_part<<<1184, 128>>>(x, Wa1);
    rescore_fin<<<148, 128>>>(ba1, Wa2, ba2);
    tail_k<<<1, 256>>>(x, out);
    cls_kernel<<<HDIM / 32, 256>>>(Wc1, bc1, Wc2, out);
}

// round 16
// speedup vs baseline: 1.4173x; 1.0153x over previous
#include <cuda_runtime.h>
#include <cuda_bf16.h>
#include <math.h>
#include <float.h>
#include <stdint.h>

#define N_ROWS 100000
#define DDIM 1024
#define ADIM 128
#define HDIM 256
#define KSEL 16
#define MAXC 4096
#define NHIST 8192
#define HSHIFT 19
#define CUSH 64u
#define GEMM_BLKS 782       // ceil(100000/128)

// ================= scratch (device globals; no allocation) =================
__device__ __align__(16) float g_scores[N_ROWS];
__device__ __align__(16) __nv_bfloat16 g_Bbf[ADIM * DDIM];   // Wa1^T, bf16, [n][k]
__device__ __align__(16) unsigned g_hist[NHIST];
__device__ int      g_ncand;
__device__ unsigned g_thresh;
__device__ int      g_cand_i[MAXC];
__device__ float    g_cand_v[MAXC];
__device__ __align__(16) float g_cand_part[(size_t)MAXC * 8 * ADIM]; // [c][slice][n]
__device__ int      g_topidx[KSEL];
__device__ float    g_attnw[KSEL];
__device__ float    g_emb[DDIM];

__device__ __forceinline__ uint32_t smem_u32(const void* p) {
    uint32_t a;
    asm("{ .reg .u64 tmp; cvta.to.shared.u64 tmp, %1; cvt.u32.u64 %0, tmp; }"
        : "=r"(a) : "l"(p));
    return a;
}

__device__ __forceinline__ unsigned fliporder(float f) {
    unsigned u = __float_as_uint(f);
    return (u & 0x80000000u) ? ~u : (u | 0x80000000u);
}

// ================= prep: vectorized zeroing (all blocks) + Wa1 transpose (blocks 0-31) =================
// grid = 98 blocks x 256 threads
__global__ void __launch_bounds__(256) prep_k(const float* __restrict__ Wa1,
                                              float* __restrict__ out,
                                              const float* __restrict__ bc2) {
    __shared__ float s[64][65];
    const int t = threadIdx.x;
    const int i = blockIdx.x * 256 + t;     // 0..25087

    // zero full_weights region out[1025 .. 1025+100000)
    // aligned float4 span: [1028, 101024) = 24999 chunks; scalars: 1025,1026,1027,101024
    if (i < 24999)
        *(float4*)(out + 1028 + i * 4) = make_float4(0.f, 0.f, 0.f, 0.f);
    if (i == 0) {
        out[1025] = 0.f; out[1026] = 0.f; out[1027] = 0.f; out[101024] = 0.f;
        g_ncand = 0; out[0] = bc2[0];
    }
    // zero histogram: 8192 bins = 2048 uint4
    if (i < 2048)
        *(uint4*)(g_hist + i * 4) = make_uint4(0u, 0u, 0u, 0u);

    if (blockIdx.x < 32) {
        const int k0 = (blockIdx.x >> 1) * 64;
        const int n0 = (blockIdx.x & 1) * 64;
#pragma unroll
        for (int e = 0; e < 16; e++) {
            int idx = e * 256 + t;
            int kk = idx >> 6, nn = idx & 63;
            s[kk][nn] = Wa1[(size_t)(k0 + kk) * ADIM + n0 + nn];
        }
        __syncthreads();
#pragma unroll
        for (int e = 0; e < 16; e++) {
            int idx = e * 256 + t;
            int nn = idx >> 6, kk = idx & 63;
            g_Bbf[(size_t)(n0 + nn) * DDIM + k0 + kk] = __float2bfloat16(s[kk][nn]);
        }
    }
}

// ================= main GEMM: approx scores via mma.sync bf16 (round-11 proven) =================
#define SROW 40   // padded row stride (bf16); 80B rows, 16B-aligned offsets

__global__ void __launch_bounds__(256, 2) gemm_scores(
    const float* __restrict__ x, const float* __restrict__ ba1,
    const float* __restrict__ Wa2, const float* __restrict__ ba2)
{
    __shared__ __align__(16) __nv_bfloat16 sA[2][128][SROW];
    __shared__ __align__(16) __nv_bfloat16 sB[2][128][SROW];
    __shared__ float s_part[4][128];
    __shared__ float s_b1[ADIM], s_w2[ADIM];

    const int t = threadIdx.x;
    const int w = t >> 5, lane = t & 31;
    const int wm = w & 1, wn = w >> 1;
    const size_t block_m = (size_t)blockIdx.x * 128;

    if (t < ADIM) { s_b1[t] = ba1[t]; s_w2[t] = Wa2[t]; }

    const int arow = t >> 3;
    const int acol = (t & 7) * 4;
    const float* xptr = x + (block_m + (size_t)arow) * DDIM + acol;
    bool aok[4];
#pragma unroll
    for (int i = 0; i < 4; i++) aok[i] = (block_m + arow + 32 * i) < N_ROWS;

    const int brow = t >> 2;
    const int bcol8 = (t & 3) * 8;
    const __nv_bfloat16* gB = g_Bbf + (size_t)brow * DDIM + bcol8;

    const int arow_l = ((lane >> 3) & 1) * 8 + (lane & 7);
    const int acol_l = (lane >> 4) * 8;
    const int brow_l = ((lane >> 4) & 1) * 8 + (lane & 7);
    const int bcol_l = ((lane >> 3) & 1) * 8;

    const uint32_t sa_base = smem_u32(&sA[0][0][0]);
    const uint32_t sb_base = smem_u32(&sB[0][0][0]);
    const uint32_t bufstride = 128 * SROW * 2;

    float acc[4][4][4];
#pragma unroll
    for (int i = 0; i < 4; i++)
#pragma unroll
        for (int j = 0; j < 4; j++)
#pragma unroll
            for (int q = 0; q < 4; q++) acc[i][j][q] = 0.f;

    float4 pa0, pa1, pa2, pa3;
    pa0 = aok[0] ? *(const float4*)(xptr)             : make_float4(0,0,0,0);
    pa1 = aok[1] ? *(const float4*)(xptr + 32 * DDIM) : make_float4(0,0,0,0);
    pa2 = aok[2] ? *(const float4*)(xptr + 64 * DDIM) : make_float4(0,0,0,0);
    pa3 = aok[3] ? *(const float4*)(xptr + 96 * DDIM) : make_float4(0,0,0,0);
    {
        uint32_t d0 = sb_base + (uint32_t)((brow * SROW + bcol8) * 2);
        uint32_t d1 = sb_base + (uint32_t)(((brow + 64) * SROW + bcol8) * 2);
        asm volatile("cp.async.cg.shared.global [%0], [%1], 16;" :: "r"(d0), "l"(gB) : "memory");
        asm volatile("cp.async.cg.shared.global [%0], [%1], 16;" :: "r"(d1), "l"(gB + 64 * DDIM) : "memory");
        asm volatile("cp.async.commit_group;" ::: "memory");
    }

#pragma unroll 1
    for (int c = 0; c < 32; c++) {
        const int buf = c & 1;
        {
            __nv_bfloat16* base = &sA[buf][0][0];
            __nv_bfloat162 q0 = __floats2bfloat162_rn(pa0.x, pa0.y);
            __nv_bfloat162 q1 = __floats2bfloat162_rn(pa0.z, pa0.w);
            *(uint2*)(base + arow * SROW + acol) = make_uint2(*(uint32_t*)&q0, *(uint32_t*)&q1);
            q0 = __floats2bfloat162_rn(pa1.x, pa1.y); q1 = __floats2bfloat162_rn(pa1.z, pa1.w);
            *(uint2*)(base + (arow + 32) * SROW + acol) = make_uint2(*(uint32_t*)&q0, *(uint32_t*)&q1);
            q0 = __floats2bfloat162_rn(pa2.x, pa2.y); q1 = __floats2bfloat162_rn(pa2.z, pa2.w);
            *(uint2*)(base + (arow + 64) * SROW + acol) = make_uint2(*(uint32_t*)&q0, *(uint32_t*)&q1);
            q0 = __floats2bfloat162_rn(pa3.x, pa3.y); q1 = __floats2bfloat162_rn(pa3.z, pa3.w);
            *(uint2*)(base + (arow + 96) * SROW + acol) = make_uint2(*(uint32_t*)&q0, *(uint32_t*)&q1);
        }
        if (c < 31) {
            const int k0 = (c + 1) * 32;
            pa0 = aok[0] ? *(const float4*)(xptr + k0)             : make_float4(0,0,0,0);
            pa1 = aok[1] ? *(const float4*)(xptr + 32 * DDIM + k0) : make_float4(0,0,0,0);
            pa2 = aok[2] ? *(const float4*)(xptr + 64 * DDIM + k0) : make_float4(0,0,0,0);
            pa3 = aok[3] ? *(const float4*)(xptr + 96 * DDIM + k0) : make_float4(0,0,0,0);
        }
        asm volatile("cp.async.wait_group 0;" ::: "memory");
        __syncthreads();
        if (c < 31) {
            const int k0 = (c + 1) * 32;
            uint32_t nb = sb_base + (uint32_t)(buf ^ 1) * bufstride;
            uint32_t d0 = nb + (uint32_t)((brow * SROW + bcol8) * 2);
            uint32_t d1 = nb + (uint32_t)(((brow + 64) * SROW + bcol8) * 2);
            asm volatile("cp.async.cg.shared.global [%0], [%1], 16;" :: "r"(d0), "l"(gB + k0) : "memory");
            asm volatile("cp.async.cg.shared.global [%0], [%1], 16;" :: "r"(d1), "l"(gB + 64 * DDIM + k0) : "memory");
            asm volatile("cp.async.commit_group;" ::: "memory");
        }
        const uint32_t sa = sa_base + buf * bufstride;
        const uint32_t sb = sb_base + buf * bufstride;
#pragma unroll
        for (int ks = 0; ks < 2; ks++) {
            uint32_t a[4][4];
#pragma unroll
            for (int mi = 0; mi < 4; mi++) {
                uint32_t addr = sa + (((wm * 64 + mi * 16 + arow_l) * SROW) + ks * 16 + acol_l) * 2;
                asm volatile("ldmatrix.sync.aligned.m8n8.x4.shared.b16 {%0,%1,%2,%3}, [%4];"
                    : "=r"(a[mi][0]), "=r"(a[mi][1]), "=r"(a[mi][2]), "=r"(a[mi][3]) : "r"(addr));
            }
            uint32_t b[4][2];
#pragma unroll
            for (int njp = 0; njp < 2; njp++) {
                uint32_t addr = sb + (((wn * 32 + njp * 16 + brow_l) * SROW) + ks * 16 + bcol_l) * 2;
                uint32_t r0, r1, r2, r3;
                asm volatile("ldmatrix.sync.aligned.m8n8.x4.shared.b16 {%0,%1,%2,%3}, [%4];"
                    : "=r"(r0), "=r"(r1), "=r"(r2), "=r"(r3) : "r"(addr));
                b[njp * 2 + 0][0] = r0; b[njp * 2 + 0][1] = r1;
                b[njp * 2 + 1][0] = r2; b[njp * 2 + 1][1] = r3;
            }
#pragma unroll
            for (int mi = 0; mi < 4; mi++)
#pragma unroll
                for (int nj = 0; nj < 4; nj++) {
                    asm volatile(
                        "mma.sync.aligned.m16n8k16.row.col.f32.bf16.bf16.f32 "
                        "{%0,%1,%2,%3}, {%4,%5,%6,%7}, {%8,%9}, {%0,%1,%2,%3};"
                        : "+f"(acc[mi][nj][0]), "+f"(acc[mi][nj][1]),
                          "+f"(acc[mi][nj][2]), "+f"(acc[mi][nj][3])
                        : "r"(a[mi][0]), "r"(a[mi][1]), "r"(a[mi][2]), "r"(a[mi][3]),
                          "r"(b[nj][0]), "r"(b[nj][1]));
                }
        }
    }

    __syncthreads();
#pragma unroll
    for (int mi = 0; mi < 4; mi++) {
        float p0 = 0.f, p1 = 0.f;
#pragma unroll
        for (int nj = 0; nj < 4; nj++) {
            int col = wn * 32 + nj * 8 + (lane & 3) * 2;
            float th;
            float v0 = acc[mi][nj][0] + s_b1[col];
            asm("tanh.approx.f32 %0, %1;" : "=f"(th) : "f"(v0));
            p0 = fmaf(th, s_w2[col], p0);
            float v1 = acc[mi][nj][1] + s_b1[col + 1];
            asm("tanh.approx.f32 %0, %1;" : "=f"(th) : "f"(v1));
            p0 = fmaf(th, s_w2[col + 1], p0);
            float v2 = acc[mi][nj][2] + s_b1[col];
            asm("tanh.approx.f32 %0, %1;" : "=f"(th) : "f"(v2));
            p1 = fmaf(th, s_w2[col], p1);
            float v3 = acc[mi][nj][3] + s_b1[col + 1];
            asm("tanh.approx.f32 %0, %1;" : "=f"(th) : "f"(v3));
            p1 = fmaf(th, s_w2[col + 1], p1);
        }
        p0 += __shfl_xor_sync(0xffffffffu, p0, 1);
        p0 += __shfl_xor_sync(0xffffffffu, p0, 2);
        p1 += __shfl_xor_sync(0xffffffffu, p1, 1);
        p1 += __shfl_xor_sync(0xffffffffu, p1, 2);
        if ((lane & 3) == 0) {
            int r = wm * 64 + mi * 16 + (lane >> 2);
            s_part[wn][r]     = p0;
            s_part[wn][r + 8] = p1;
        }
    }
    __syncthreads();
    if (t < 128) {
        size_t m = block_m + (size_t)t;
        if (m < N_ROWS) {
            float sc = s_part[0][t] + s_part[1][t] + s_part[2][t] + s_part[3][t] + ba2[0];
            g_scores[m] = sc;
            atomicAdd(&g_hist[fliporder(sc) >> HSHIFT], 1u);
        }
    }
}

// ================= scan: 1024 threads, 8 bins/thread (uint4), suffix-scan =================
__global__ void __launch_bounds__(1024) scan_k() {
    __shared__ unsigned s_wsum[32];
    __shared__ int s_seg;
    __shared__ unsigned s_cum;
    const int t = threadIdx.x;
    const int lane = t & 31, wid = t >> 5;

    uint4 h0 = *(const uint4*)&g_hist[t * 8];
    uint4 h1 = *(const uint4*)&g_hist[t * 8 + 4];
    unsigned part = h0.x + h0.y + h0.z + h0.w + h1.x + h1.y + h1.z + h1.w;

    unsigned sfx = part;
#pragma unroll
    for (int off = 1; off < 32; off <<= 1) {
        unsigned v = __shfl_down_sync(0xffffffffu, sfx, off);
        if (lane + off < 32) sfx += v;
    }
    if (lane == 0) s_wsum[wid] = sfx;
    __syncthreads();
    unsigned above = 0;
    for (int ww = wid + 1; ww < 32; ww++) above += s_wsum[ww];
    unsigned ssum = sfx + above;
    if (ssum >= CUSH && (ssum - part) < CUSH) { s_seg = t; s_cum = ssum - part; }
    __syncthreads();
    if (t == 0) {
        unsigned cum = s_cum;
        int b = 7;
        for (; b > 0; b--) { cum += g_hist[s_seg * 8 + b]; if (cum >= CUSH) break; }
        g_thresh = ((unsigned)(s_seg * 8 + b)) << HSHIFT;
    }
}

// ================= collect: float4 stream against precomputed threshold =================
// grid 49 x 512 threads, 4 scores/thread
__global__ void __launch_bounds__(512) collect_k() {
    const unsigned thresh = g_thresh;
    int i = blockIdx.x * 512 + threadIdx.x;     // chunk index, 25000 chunks
    if (i < 25000) {
        float4 v = *(const float4*)(g_scores + i * 4);
        int base = i * 4;
        if (fliporder(v.x) >= thresh) { int p = atomicAdd(&g_ncand, 1); if (p < MAXC) g_cand_i[p] = base;     }
        if (fliporder(v.y) >= thresh) { int p = atomicAdd(&g_ncand, 1); if (p < MAXC) g_cand_i[p] = base + 1; }
        if (fliporder(v.z) >= thresh) { int p = atomicAdd(&g_ncand, 1); if (p < MAXC) g_cand_i[p] = base + 2; }
        if (fliporder(v.w) >= thresh) { int p = atomicAdd(&g_ncand, 1); if (p < MAXC) g_cand_i[p] = base + 3; }
    }
}

// ================= rescore phase 1: split-K (8 slices of 128) =================
__global__ void __launch_bounds__(128) rescore_part(
    const float* __restrict__ x, const float* __restrict__ Wa1)
{
    __shared__ float sx[128];
    int nc = g_ncand; if (nc > MAXC) nc = MAXC;
    const int nwork = nc * 8;
    const int t = threadIdx.x;
    for (int wk = blockIdx.x; wk < nwork; wk += gridDim.x) {
        const int c = wk >> 3, s = wk & 7;
        const int row = g_cand_i[c];
        sx[t] = x[(size_t)row * DDIM + s * 128 + t];
        __syncthreads();
        const float* Wp = Wa1 + (size_t)(s * 128) * ADIM + t;
        float a = 0.f;
#pragma unroll 8
        for (int k = 0; k < 128; k++)
            a = fmaf(sx[k], Wp[(size_t)k * ADIM], a);
        g_cand_part[((size_t)c * 8 + s) * ADIM + t] = a;
        __syncthreads();
    }
}

// ================= rescore phase 2: combine partials, tanh, reduce =================
__global__ void __launch_bounds__(128) rescore_fin(
    const float* __restrict__ ba1, const float* __restrict__ Wa2,
    const float* __restrict__ ba2)
{
    __shared__ float sred[4];
    int nc = g_ncand; if (nc > MAXC) nc = MAXC;
    const int t = threadIdx.x;
    const float b1 = ba1[t], w2 = Wa2[t], b2 = ba2[0];
    for (int c = blockIdx.x; c < nc; c += gridDim.x) {
        const float* p = g_cand_part + (size_t)c * 8 * ADIM;
        float a = 0.f;
#pragma unroll
        for (int j = 0; j < 8; j++) a += p[j * ADIM + t];
        float v = tanhf(a + b1) * w2;
#pragma unroll
        for (int off = 16; off >= 1; off >>= 1)
            v += __shfl_down_sync(0xffffffffu, v, off);
        if ((t & 31) == 0) sred[t >> 5] = v;
        __syncthreads();
        if (t == 0) g_cand_v[c] = sred[0] + sred[1] + sred[2] + sred[3] + b2;
        __syncthreads();
    }
}

// ================= tail: exact top-16 + softmax + scatter + embedding =================
__global__ void __launch_bounds__(256) tail_k(const float* __restrict__ x,
                                              float* __restrict__ out) {
    __shared__ float sv[MAXC];
    __shared__ int   si[MAXC];
    __shared__ float wv[8];
    __shared__ int   wi[8];
    __shared__ float topv[KSEL];
    __shared__ int   topi[KSEL];
    __shared__ float topw[KSEL];
    const int t = threadIdx.x;
    int nc = g_ncand; if (nc > MAXC) nc = MAXC;
    for (int i = t; i < nc; i += 256) { sv[i] = g_cand_v[i]; si[i] = g_cand_i[i]; }
    __syncthreads();
    for (int it = 0; it < KSEL; it++) {
        float bv = -FLT_MAX; int bi = 0x7fffffff;
        for (int i = t; i < nc; i += 256) {
            float v = sv[i]; int gi = si[i];
            if (v > bv || (v == bv && gi < bi)) { bv = v; bi = gi; }
        }
#pragma unroll
        for (int off = 16; off >= 1; off >>= 1) {
            float ov = __shfl_down_sync(0xffffffffu, bv, off);
            int   oi = __shfl_down_sync(0xffffffffu, bi, off);
            if (ov > bv || (ov == bv && oi < bi)) { bv = ov; bi = oi; }
        }
        if ((t & 31) == 0) { wv[t >> 5] = bv; wi[t >> 5] = bi; }
        __syncthreads();
        if (t == 0) {
            for (int w = 1; w < 8; w++)
                if (wv[w] > wv[0] || (wv[w] == wv[0] && wi[w] < wi[0])) { wv[0] = wv[w]; wi[0] = wi[w]; }
            topv[it] = wv[0]; topi[it] = wi[0];
        }
        __syncthreads();
        int wini = topi[it];
        for (int i = t; i < nc; i += 256)
            if (si[i] == wini) sv[i] = -FLT_MAX;
        __syncthreads();
    }
    if (t == 0) {
        float m = topv[0];
        float e[KSEL];
        float ssum = 0.f;
        for (int j = 0; j < KSEL; j++) { e[j] = expf(topv[j] - m); ssum += e[j]; }
        float inv = 1.f / ssum;
        for (int j = 0; j < KSEL; j++) {
            float wgt = e[j] * inv;
            topw[j] = wgt;
            g_attnw[j]  = wgt;
            g_topidx[j] = topi[j];
            out[1 + DDIM + N_ROWS + j] = (float)topi[j];
            out[1 + DDIM + topi[j]]    = wgt;
        }
    }
    __syncthreads();
    for (int d = t; d < DDIM; d += 256) {
        float s = 0.f;
#pragma unroll
        for (int j = 0; j < KSEL; j++)
            s += topw[j] * x[(size_t)topi[j] * DDIM + d];
        g_emb[d]   = s;
        out[1 + d] = s;
    }
}

// ================= classifier: 8 blocks, partial logits via atomicAdd =================
__global__ void __launch_bounds__(256) cls_kernel(
    const float* __restrict__ Wc1, const float* __restrict__ bc1,
    const float* __restrict__ Wc2, float* __restrict__ out)
{
    __shared__ float e[DDIM];
    __shared__ float sred[8][32];
    const int t = threadIdx.x;
    const int j = blockIdx.x * 32 + (t & 31);
    const int dp = (t >> 5) * 128;
    for (int d = t; d < DDIM; d += 256) e[d] = g_emb[d];
    __syncthreads();
    float acc = 0.f;
#pragma unroll 16
    for (int d = 0; d < 128; d++)
        acc = fmaf(e[dp + d], Wc1[(size_t)(dp + d) * HDIM + j], acc);
    sred[t >> 5][t & 31] = acc;
    __syncthreads();
    if (t < 32) {
        float a = sred[0][t] + sred[1][t] + sred[2][t] + sred[3][t]
                + sred[4][t] + sred[5][t] + sred[6][t] + sred[7][t];
        int jj = blockIdx.x * 32 + t;
        float h = fmaxf(a + bc1[jj], 0.f);
        float part = h * Wc2[jj];
#pragma unroll
        for (int off = 16; off >= 1; off >>= 1)
            part += __shfl_down_sync(0xffffffffu, part, off);
        if (t == 0) atomicAdd(out, part);
    }
}

// ================= launch =================
extern "C" void kernel_launch(void* const* d_in, const int* in_sizes, int n_in,
                              void* d_out, int out_size)
{
    const float* x   = (const float*)d_in[0];
    const float* Wa1 = (const float*)d_in[1];
    const float* ba1 = (const float*)d_in[2];
    const float* Wa2 = (const float*)d_in[3];
    const float* ba2 = (const float*)d_in[4];
    const float* Wc1 = (const float*)d_in[5];
    const float* bc1 = (const float*)d_in[6];
    const float* Wc2 = (const float*)d_in[7];
    const float* bc2 = (const float*)d_in[8];
    float* out = (float*)d_out;

    prep_k<<<98, 256>>>(Wa1, out, bc2);
    gemm_scores<<<GEMM_BLKS, 256>>>(x, ba1, Wa2, ba2);
    scan_k<<<1, 1024>>>();
    collect_k<<<49, 512>>>();
    rescore_part<<<1184, 128>>>(x, Wa1);
    rescore_fin<<<148, 128>>>(ba1, Wa2, ba2);
    tail_k<<<1, 256>>>(x, out);
    cls_kernel<<<HDIM / 32, 256>>>(Wc1, bc1, Wc2, out);
}

// round 17
// speedup vs baseline: 1.5728x; 1.1096x over previous
#include <cuda_runtime.h>
#include <cuda_bf16.h>
#include <math.h>
#include <float.h>
#include <stdint.h>

#define N_ROWS 100000
#define DDIM 1024
#define ADIM 128
#define HDIM 256
#define KSEL 16
#define MAXC 4096
#define NHIST 8192
#define HSHIFT 19
#define CUSH 64u
#define GEMM_BLKS 782       // ceil(100000/128)

// ================= scratch (device globals; no allocation) =================
__device__ __align__(16) float g_scores[N_ROWS];
__device__ __align__(16) __nv_bfloat16 g_Bbf[ADIM * DDIM];   // Wa1^T, bf16, [n][k]
__device__ __align__(16) unsigned g_hist[NHIST];
__device__ int      g_ncand;
__device__ int      g_cand_i[MAXC];
__device__ float    g_cand_v[MAXC];
__device__ __align__(16) float g_cand_part[(size_t)MAXC * 8 * ADIM]; // [c][slice][n]
__device__ int      g_topidx[KSEL];
__device__ float    g_attnw[KSEL];
__device__ float    g_emb[DDIM];

__device__ __forceinline__ uint32_t smem_u32(const void* p) {
    uint32_t a;
    asm("{ .reg .u64 tmp; cvta.to.shared.u64 tmp, %1; cvt.u32.u64 %0, tmp; }"
        : "=r"(a) : "l"(p));
    return a;
}

__device__ __forceinline__ unsigned fliporder(float f) {
    unsigned u = __float_as_uint(f);
    return (u & 0x80000000u) ? ~u : (u | 0x80000000u);
}

// ================= prep: vectorized zeroing (all blocks) + Wa1 transpose (blocks 0-31) =================
// grid = 98 blocks x 256 threads
__global__ void __launch_bounds__(256) prep_k(const float* __restrict__ Wa1,
                                              float* __restrict__ out,
                                              const float* __restrict__ bc2) {
    __shared__ float s[64][65];
    const int t = threadIdx.x;
    const int i = blockIdx.x * 256 + t;     // 0..25087

    if (i < 24999)
        *(float4*)(out + 1028 + i * 4) = make_float4(0.f, 0.f, 0.f, 0.f);
    if (i == 0) {
        out[1025] = 0.f; out[1026] = 0.f; out[1027] = 0.f; out[101024] = 0.f;
        g_ncand = 0; out[0] = bc2[0];
    }
    if (i < 2048)
        *(uint4*)(g_hist + i * 4) = make_uint4(0u, 0u, 0u, 0u);

    if (blockIdx.x < 32) {
        const int k0 = (blockIdx.x >> 1) * 64;
        const int n0 = (blockIdx.x & 1) * 64;
#pragma unroll
        for (int e = 0; e < 16; e++) {
            int idx = e * 256 + t;
            int kk = idx >> 6, nn = idx & 63;
            s[kk][nn] = Wa1[(size_t)(k0 + kk) * ADIM + n0 + nn];
        }
        __syncthreads();
#pragma unroll
        for (int e = 0; e < 16; e++) {
            int idx = e * 256 + t;
            int nn = idx >> 6, kk = idx & 63;
            g_Bbf[(size_t)(n0 + nn) * DDIM + k0 + kk] = __float2bfloat16(s[kk][nn]);
        }
    }
}

// ================= main GEMM: approx scores via mma.sync bf16 (round-11 proven) =================
#define SROW 40   // padded row stride (bf16); 80B rows, 16B-aligned offsets

__global__ void __launch_bounds__(256, 2) gemm_scores(
    const float* __restrict__ x, const float* __restrict__ ba1,
    const float* __restrict__ Wa2, const float* __restrict__ ba2)
{
    __shared__ __align__(16) __nv_bfloat16 sA[2][128][SROW];
    __shared__ __align__(16) __nv_bfloat16 sB[2][128][SROW];
    __shared__ float s_part[4][128];
    __shared__ float s_b1[ADIM], s_w2[ADIM];

    const int t = threadIdx.x;
    const int w = t >> 5, lane = t & 31;
    const int wm = w & 1, wn = w >> 1;
    const size_t block_m = (size_t)blockIdx.x * 128;

    if (t < ADIM) { s_b1[t] = ba1[t]; s_w2[t] = Wa2[t]; }

    const int arow = t >> 3;
    const int acol = (t & 7) * 4;
    const float* xptr = x + (block_m + (size_t)arow) * DDIM + acol;
    bool aok[4];
#pragma unroll
    for (int i = 0; i < 4; i++) aok[i] = (block_m + arow + 32 * i) < N_ROWS;

    const int brow = t >> 2;
    const int bcol8 = (t & 3) * 8;
    const __nv_bfloat16* gB = g_Bbf + (size_t)brow * DDIM + bcol8;

    const int arow_l = ((lane >> 3) & 1) * 8 + (lane & 7);
    const int acol_l = (lane >> 4) * 8;
    const int brow_l = ((lane >> 4) & 1) * 8 + (lane & 7);
    const int bcol_l = ((lane >> 3) & 1) * 8;

    const uint32_t sa_base = smem_u32(&sA[0][0][0]);
    const uint32_t sb_base = smem_u32(&sB[0][0][0]);
    const uint32_t bufstride = 128 * SROW * 2;

    float acc[4][4][4];
#pragma unroll
    for (int i = 0; i < 4; i++)
#pragma unroll
        for (int j = 0; j < 4; j++)
#pragma unroll
            for (int q = 0; q < 4; q++) acc[i][j][q] = 0.f;

    float4 pa0, pa1, pa2, pa3;
    pa0 = aok[0] ? *(const float4*)(xptr)             : make_float4(0,0,0,0);
    pa1 = aok[1] ? *(const float4*)(xptr + 32 * DDIM) : make_float4(0,0,0,0);
    pa2 = aok[2] ? *(const float4*)(xptr + 64 * DDIM) : make_float4(0,0,0,0);
    pa3 = aok[3] ? *(const float4*)(xptr + 96 * DDIM) : make_float4(0,0,0,0);
    {
        uint32_t d0 = sb_base + (uint32_t)((brow * SROW + bcol8) * 2);
        uint32_t d1 = sb_base + (uint32_t)(((brow + 64) * SROW + bcol8) * 2);
        asm volatile("cp.async.cg.shared.global [%0], [%1], 16;" :: "r"(d0), "l"(gB) : "memory");
        asm volatile("cp.async.cg.shared.global [%0], [%1], 16;" :: "r"(d1), "l"(gB + 64 * DDIM) : "memory");
        asm volatile("cp.async.commit_group;" ::: "memory");
    }

#pragma unroll 1
    for (int c = 0; c < 32; c++) {
        const int buf = c & 1;
        {
            __nv_bfloat16* base = &sA[buf][0][0];
            __nv_bfloat162 q0 = __floats2bfloat162_rn(pa0.x, pa0.y);
            __nv_bfloat162 q1 = __floats2bfloat162_rn(pa0.z, pa0.w);
            *(uint2*)(base + arow * SROW + acol) = make_uint2(*(uint32_t*)&q0, *(uint32_t*)&q1);
            q0 = __floats2bfloat162_rn(pa1.x, pa1.y); q1 = __floats2bfloat162_rn(pa1.z, pa1.w);
            *(uint2*)(base + (arow + 32) * SROW + acol) = make_uint2(*(uint32_t*)&q0, *(uint32_t*)&q1);
            q0 = __floats2bfloat162_rn(pa2.x, pa2.y); q1 = __floats2bfloat162_rn(pa2.z, pa2.w);
            *(uint2*)(base + (arow + 64) * SROW + acol) = make_uint2(*(uint32_t*)&q0, *(uint32_t*)&q1);
            q0 = __floats2bfloat162_rn(pa3.x, pa3.y); q1 = __floats2bfloat162_rn(pa3.z, pa3.w);
            *(uint2*)(base + (arow + 96) * SROW + acol) = make_uint2(*(uint32_t*)&q0, *(uint32_t*)&q1);
        }
        if (c < 31) {
            const int k0 = (c + 1) * 32;
            pa0 = aok[0] ? *(const float4*)(xptr + k0)             : make_float4(0,0,0,0);
            pa1 = aok[1] ? *(const float4*)(xptr + 32 * DDIM + k0) : make_float4(0,0,0,0);
            pa2 = aok[2] ? *(const float4*)(xptr + 64 * DDIM + k0) : make_float4(0,0,0,0);
            pa3 = aok[3] ? *(const float4*)(xptr + 96 * DDIM + k0) : make_float4(0,0,0,0);
        }
        asm volatile("cp.async.wait_group 0;" ::: "memory");
        __syncthreads();
        if (c < 31) {
            const int k0 = (c + 1) * 32;
            uint32_t nb = sb_base + (uint32_t)(buf ^ 1) * bufstride;
            uint32_t d0 = nb + (uint32_t)((brow * SROW + bcol8) * 2);
            uint32_t d1 = nb + (uint32_t)(((brow + 64) * SROW + bcol8) * 2);
            asm volatile("cp.async.cg.shared.global [%0], [%1], 16;" :: "r"(d0), "l"(gB + k0) : "memory");
            asm volatile("cp.async.cg.shared.global [%0], [%1], 16;" :: "r"(d1), "l"(gB + 64 * DDIM + k0) : "memory");
            asm volatile("cp.async.commit_group;" ::: "memory");
        }
        const uint32_t sa = sa_base + buf * bufstride;
        const uint32_t sb = sb_base + buf * bufstride;
#pragma unroll
        for (int ks = 0; ks < 2; ks++) {
            uint32_t a[4][4];
#pragma unroll
            for (int mi = 0; mi < 4; mi++) {
                uint32_t addr = sa + (((wm * 64 + mi * 16 + arow_l) * SROW) + ks * 16 + acol_l) * 2;
                asm volatile("ldmatrix.sync.aligned.m8n8.x4.shared.b16 {%0,%1,%2,%3}, [%4];"
                    : "=r"(a[mi][0]), "=r"(a[mi][1]), "=r"(a[mi][2]), "=r"(a[mi][3]) : "r"(addr));
            }
            uint32_t b[4][2];
#pragma unroll
            for (int njp = 0; njp < 2; njp++) {
                uint32_t addr = sb + (((wn * 32 + njp * 16 + brow_l) * SROW) + ks * 16 + bcol_l) * 2;
                uint32_t r0, r1, r2, r3;
                asm volatile("ldmatrix.sync.aligned.m8n8.x4.shared.b16 {%0,%1,%2,%3}, [%4];"
                    : "=r"(r0), "=r"(r1), "=r"(r2), "=r"(r3) : "r"(addr));
                b[njp * 2 + 0][0] = r0; b[njp * 2 + 0][1] = r1;
                b[njp * 2 + 1][0] = r2; b[njp * 2 + 1][1] = r3;
            }
#pragma unroll
            for (int mi = 0; mi < 4; mi++)
#pragma unroll
                for (int nj = 0; nj < 4; nj++) {
                    asm volatile(
                        "mma.sync.aligned.m16n8k16.row.col.f32.bf16.bf16.f32 "
                        "{%0,%1,%2,%3}, {%4,%5,%6,%7}, {%8,%9}, {%0,%1,%2,%3};"
                        : "+f"(acc[mi][nj][0]), "+f"(acc[mi][nj][1]),
                          "+f"(acc[mi][nj][2]), "+f"(acc[mi][nj][3])
                        : "r"(a[mi][0]), "r"(a[mi][1]), "r"(a[mi][2]), "r"(a[mi][3]),
                          "r"(b[nj][0]), "r"(b[nj][1]));
                }
        }
    }

    __syncthreads();
#pragma unroll
    for (int mi = 0; mi < 4; mi++) {
        float p0 = 0.f, p1 = 0.f;
#pragma unroll
        for (int nj = 0; nj < 4; nj++) {
            int col = wn * 32 + nj * 8 + (lane & 3) * 2;
            float th;
            float v0 = acc[mi][nj][0] + s_b1[col];
            asm("tanh.approx.f32 %0, %1;" : "=f"(th) : "f"(v0));
            p0 = fmaf(th, s_w2[col], p0);
            float v1 = acc[mi][nj][1] + s_b1[col + 1];
            asm("tanh.approx.f32 %0, %1;" : "=f"(th) : "f"(v1));
            p0 = fmaf(th, s_w2[col + 1], p0);
            float v2 = acc[mi][nj][2] + s_b1[col];
            asm("tanh.approx.f32 %0, %1;" : "=f"(th) : "f"(v2));
            p1 = fmaf(th, s_w2[col], p1);
            float v3 = acc[mi][nj][3] + s_b1[col + 1];
            asm("tanh.approx.f32 %0, %1;" : "=f"(th) : "f"(v3));
            p1 = fmaf(th, s_w2[col + 1], p1);
        }
        p0 += __shfl_xor_sync(0xffffffffu, p0, 1);
        p0 += __shfl_xor_sync(0xffffffffu, p0, 2);
        p1 += __shfl_xor_sync(0xffffffffu, p1, 1);
        p1 += __shfl_xor_sync(0xffffffffu, p1, 2);
        if ((lane & 3) == 0) {
            int r = wm * 64 + mi * 16 + (lane >> 2);
            s_part[wn][r]     = p0;
            s_part[wn][r + 8] = p1;
        }
    }
    __syncthreads();
    if (t < 128) {
        size_t m = block_m + (size_t)t;
        if (m < N_ROWS) {
            float sc = s_part[0][t] + s_part[1][t] + s_part[2][t] + s_part[3][t] + ba2[0];
            g_scores[m] = sc;
            atomicAdd(&g_hist[fliporder(sc) >> HSHIFT], 1u);
        }
    }
}

// ================= collect: in-block threshold scan (49 blocks) + candidate collect =================
// grid 49 x 512 threads; each block redundantly computes the threshold from the
// (L2-hot) histogram (16 bins/thread, warp suffix scan), then streams 4 scores/thread.
__global__ void __launch_bounds__(512) collect_k() {
    __shared__ unsigned s_wsum[16];
    __shared__ unsigned s_thresh;
    __shared__ int s_seg;
    __shared__ unsigned s_cum;
    const int t = threadIdx.x;
    const int lane = t & 31, wid = t >> 5;

    // 16 bins/thread via 4 uint4 loads
    unsigned part;
    {
        const uint4* hp = (const uint4*)(g_hist + t * 16);
        uint4 h0 = hp[0], h1 = hp[1], h2 = hp[2], h3 = hp[3];
        part = h0.x + h0.y + h0.z + h0.w + h1.x + h1.y + h1.z + h1.w
             + h2.x + h2.y + h2.z + h2.w + h3.x + h3.y + h3.z + h3.w;
    }
    unsigned sfx = part;
#pragma unroll
    for (int off = 1; off < 32; off <<= 1) {
        unsigned v = __shfl_down_sync(0xffffffffu, sfx, off);
        if (lane + off < 32) sfx += v;
    }
    if (lane == 0) s_wsum[wid] = sfx;
    __syncthreads();
    unsigned above = 0;
#pragma unroll
    for (int ww = 0; ww < 16; ww++) if (ww > wid) above += s_wsum[ww];
    unsigned ssum = sfx + above;
    if (ssum >= CUSH && (ssum - part) < CUSH) { s_seg = t; s_cum = ssum - part; }
    __syncthreads();
    if (t == 0) {
        unsigned cum = s_cum;
        int b = 15;
        for (; b > 0; b--) { cum += g_hist[s_seg * 16 + b]; if (cum >= CUSH) break; }
        s_thresh = ((unsigned)(s_seg * 16 + b)) << HSHIFT;
    }
    __syncthreads();
    const unsigned thresh = s_thresh;

    int i = blockIdx.x * 512 + t;     // chunk index, 25000 chunks
    if (i < 25000) {
        float4 v = *(const float4*)(g_scores + i * 4);
        int base = i * 4;
        if (fliporder(v.x) >= thresh) { int p = atomicAdd(&g_ncand, 1); if (p < MAXC) g_cand_i[p] = base;     }
        if (fliporder(v.y) >= thresh) { int p = atomicAdd(&g_ncand, 1); if (p < MAXC) g_cand_i[p] = base + 1; }
        if (fliporder(v.z) >= thresh) { int p = atomicAdd(&g_ncand, 1); if (p < MAXC) g_cand_i[p] = base + 2; }
        if (fliporder(v.w) >= thresh) { int p = atomicAdd(&g_ncand, 1); if (p < MAXC) g_cand_i[p] = base + 3; }
    }
}

// ================= rescore phase 1: split-K (8 slices of 128), split-k-in-block =================
// 256 threads: thread (n = t&127, h = t>>7) computes half the slice dot (64 FMAs)
__global__ void __launch_bounds__(256) rescore_part(
    const float* __restrict__ x, const float* __restrict__ Wa1)
{
    __shared__ float sx[128];
    __shared__ float spart[128];
    int nc = g_ncand; if (nc > MAXC) nc = MAXC;
    const int nwork = nc * 8;
    const int t = threadIdx.x;
    const int n = t & 127, h = t >> 7;
    for (int wk = blockIdx.x; wk < nwork; wk += gridDim.x) {
        const int c = wk >> 3, s = wk & 7;
        const int row = g_cand_i[c];
        if (t < 128) sx[t] = x[(size_t)row * DDIM + s * 128 + t];
        __syncthreads();
        const float* Wp = Wa1 + (size_t)(s * 128 + h * 64) * ADIM + n;
        const float* sxp = sx + h * 64;
        float a = 0.f;
#pragma unroll 8
        for (int k = 0; k < 64; k++)
            a = fmaf(sxp[k], Wp[(size_t)k * ADIM], a);
        if (h == 1) spart[n] = a;
        __syncthreads();
        if (h == 0)
            g_cand_part[((size_t)c * 8 + s) * ADIM + n] = a + spart[n];
        __syncthreads();
    }
}

// ================= rescore phase 2: combine partials, tanh, reduce =================
__global__ void __launch_bounds__(128) rescore_fin(
    const float* __restrict__ ba1, const float* __restrict__ Wa2,
    const float* __restrict__ ba2)
{
    __shared__ float sred[4];
    int nc = g_ncand; if (nc > MAXC) nc = MAXC;
    const int t = threadIdx.x;
    const float b1 = ba1[t], w2 = Wa2[t], b2 = ba2[0];
    for (int c = blockIdx.x; c < nc; c += gridDim.x) {
        const float* p = g_cand_part + (size_t)c * 8 * ADIM;
        float a = 0.f;
#pragma unroll
        for (int j = 0; j < 8; j++) a += p[j * ADIM + t];
        float v = tanhf(a + b1) * w2;
#pragma unroll
        for (int off = 16; off >= 1; off >>= 1)
            v += __shfl_down_sync(0xffffffffu, v, off);
        if ((t & 31) == 0) sred[t >> 5] = v;
        __syncthreads();
        if (t == 0) g_cand_v[c] = sred[0] + sred[1] + sred[2] + sred[3] + b2;
        __syncthreads();
    }
}

// ================= tail: exact top-16 + softmax + scatter + embedding =================
__global__ void __launch_bounds__(256) tail_k(const float* __restrict__ x,
                                              float* __restrict__ out) {
    __shared__ float sv[MAXC];
    __shared__ int   si[MAXC];
    __shared__ float wv[8];
    __shared__ int   wi[8];
    __shared__ float topv[KSEL];
    __shared__ int   topi[KSEL];
    __shared__ float topw[KSEL];
    const int t = threadIdx.x;
    int nc = g_ncand; if (nc > MAXC) nc = MAXC;
    for (int i = t; i < nc; i += 256) { sv[i] = g_cand_v[i]; si[i] = g_cand_i[i]; }
    __syncthreads();
    for (int it = 0; it < KSEL; it++) {
        float bv = -FLT_MAX; int bi = 0x7fffffff;
        for (int i = t; i < nc; i += 256) {
            float v = sv[i]; int gi = si[i];
            if (v > bv || (v == bv && gi < bi)) { bv = v; bi = gi; }
        }
#pragma unroll
        for (int off = 16; off >= 1; off >>= 1) {
            float ov = __shfl_down_sync(0xffffffffu, bv, off);
            int   oi = __shfl_down_sync(0xffffffffu, bi, off);
            if (ov > bv || (ov == bv && oi < bi)) { bv = ov; bi = oi; }
        }
        if ((t & 31) == 0) { wv[t >> 5] = bv; wi[t >> 5] = bi; }
        __syncthreads();
        if (t == 0) {
            for (int w = 1; w < 8; w++)
                if (wv[w] > wv[0] || (wv[w] == wv[0] && wi[w] < wi[0])) { wv[0] = wv[w]; wi[0] = wi[w]; }
            topv[it] = wv[0]; topi[it] = wi[0];
        }
        __syncthreads();
        int wini = topi[it];
        for (int i = t; i < nc; i += 256)
            if (si[i] == wini) sv[i] = -FLT_MAX;
        __syncthreads();
    }
    if (t == 0) {
        float m = topv[0];
        float e[KSEL];
        float ssum = 0.f;
        for (int j = 0; j < KSEL; j++) { e[j] = expf(topv[j] - m); ssum += e[j]; }
        float inv = 1.f / ssum;
        for (int j = 0; j < KSEL; j++) {
            float wgt = e[j] * inv;
            topw[j] = wgt;
            g_attnw[j]  = wgt;
            g_topidx[j] = topi[j];
            out[1 + DDIM + N_ROWS + j] = (float)topi[j];
            out[1 + DDIM + topi[j]]    = wgt;
        }
    }
    __syncthreads();
    for (int d = t; d < DDIM; d += 256) {
        float s = 0.f;
#pragma unroll
        for (int j = 0; j < KSEL; j++)
            s += topw[j] * x[(size_t)topi[j] * DDIM + d];
        g_emb[d]   = s;
        out[1 + d] = s;
    }
}

// ================= classifier: 8 blocks, partial logits via atomicAdd =================
__global__ void __launch_bounds__(256) cls_kernel(
    const float* __restrict__ Wc1, const float* __restrict__ bc1,
    const float* __restrict__ Wc2, float* __restrict__ out)
{
    __shared__ float e[DDIM];
    __shared__ float sred[8][32];
    const int t = threadIdx.x;
    const int j = blockIdx.x * 32 + (t & 31);
    const int dp = (t >> 5) * 128;
    for (int d = t; d < DDIM; d += 256) e[d] = g_emb[d];
    __syncthreads();
    float acc = 0.f;
#pragma unroll 16
    for (int d = 0; d < 128; d++)
        acc = fmaf(e[dp + d], Wc1[(size_t)(dp + d) * HDIM + j], acc);
    sred[t >> 5][t & 31] = acc;
    __syncthreads();
    if (t < 32) {
        float a = sred[0][t] + sred[1][t] + sred[2][t] + sred[3][t]
                + sred[4][t] + sred[5][t] + sred[6][t] + sred[7][t];
        int jj = blockIdx.x * 32 + t;
        float h = fmaxf(a + bc1[jj], 0.f);
        float part = h * Wc2[jj];
#pragma unroll
        for (int off = 16; off >= 1; off >>= 1)
            part += __shfl_down_sync(0xffffffffu, part, off);
        if (t == 0) atomicAdd(out, part);
    }
}

// ================= launch =================
extern "C" void kernel_launch(void* const* d_in, const int* in_sizes, int n_in,
                              void* d_out, int out_size)
{
    const float* x   = (const float*)d_in[0];
    const float* Wa1 = (const float*)d_in[1];
    const float* ba1 = (const float*)d_in[2];
    const float* Wa2 = (const float*)d_in[3];
    const float* ba2 = (const float*)d_in[4];
    const float* Wc1 = (const float*)d_in[5];
    const float* bc1 = (const float*)d_in[6];
    const float* Wc2 = (const float*)d_in[7];
    const float* bc2 = (const float*)d_in[8];
    float* out = (float*)d_out;

    prep_k<<<98, 256>>>(Wa1, out, bc2);
    gemm_scores<<<GEMM_BLKS, 256>>>(x, ba1, Wa2, ba2);
    collect_k<<<49, 512>>>();
    rescore_part<<<1184, 256>>>(x, Wa1);
    rescore_fin<<<148, 128>>>(ba1, Wa2, ba2);
    tail_k<<<1, 256>>>(x, out);
    cls_kernel<<<HDIM / 32, 256>>>(Wc1, bc1, Wc2, out);
}